// round 7
// baseline (speedup 1.0000x reference)
#include <cuda_runtime.h>
#include <math.h>
#include <stdint.h>

#define BB 4
#define SS 2048
#define HH 16
#define DD 128
#define DH 64    // effective qk dim (first half, duplicated in reference)
#define BM 128
#define BN 64
#define PSTR2 132   // floats per Ps row; 132*4=528 B, 16B-aligned (130 was the R5 crash)

typedef unsigned long long u64;

// Scratch (no allocations allowed): k-major preprocessed Q', K'.
// K' is stored DUPLICATED along s: [b,h,kk][2s], entry (kk,2n)=(kk,2n+1)=K'[kk][n]
__device__ float g_Qp[BB*HH*DH*SS];       // [b,h,kdim,s]     33.5 MB
__device__ float g_Kp[BB*HH*DH*2*SS];     // [b,h,kdim,2s]    67 MB
__device__ float g_inv[DH];

// ---------------- packed f32x2 helpers (sm_103a) ----------------
__device__ __forceinline__ u64 bcast2(float x) {
    u64 r;
    asm("mov.b64 %0, {%1, %1};" : "=l"(r) : "f"(x));
    return r;
}
__device__ __forceinline__ void ffma2(u64& d, u64 a, u64 b) {
    asm("fma.rn.f32x2 %0, %1, %2, %3;" : "=l"(d) : "l"(a), "l"(b), "l"(d));
}
__device__ __forceinline__ u64 mul2(u64 a, u64 b) {
    u64 d;
    asm("mul.rn.f32x2 %0, %1, %2;" : "=l"(d) : "l"(a), "l"(b));
    return d;
}
__device__ __forceinline__ void unpack2(u64 v, float& lo, float& hi) {
    asm("mov.b64 {%0, %1}, %2;" : "=f"(lo), "=f"(hi) : "l"(v));
}

// ---------------- cp.async helpers ----------------
__device__ __forceinline__ void cp_async16(uint32_t saddr, const void* gptr) {
    asm volatile("cp.async.cg.shared.global [%0], [%1], 16;"
                 :: "r"(saddr), "l"(gptr));
}
__device__ __forceinline__ void cp_commit() {
    asm volatile("cp.async.commit_group;");
}
__device__ __forceinline__ void cp_wait_all() {
    asm volatile("cp.async.wait_group 0;");
}

// ---------------- prep ----------------
__global__ void init_inv() {
    int i = threadIdx.x;
    g_inv[i] = (float)exp(-(double)i * (9.210340371976184 / 64.0)); // ln(1e4)/64
}

// Tiled transpose: q,k [b,s,h,128] (first 64 dims) * fc -> Q' [b,h,64,s],
// K' duplicated [b,h,64,2s].
__global__ void prep_qk(const float* __restrict__ q, const float* __restrict__ k) {
    __shared__ float qs[64*65];
    __shared__ float ks[64*65];
    const int st = blockIdx.x, h = blockIdx.y, b = blockIdx.z;
    const int tid = threadIdx.x;
    for (int idx = tid; idx < 64*64; idx += 256) {
        int sl = idx >> 6, i = idx & 63;
        int s = st*64 + sl;
        float fc = 2.0f * ((float)s * g_inv[i]);
        size_t gin = ((size_t)(b*SS + s)*HH + h)*DD + i;
        qs[i*65 + sl] = q[gin] * fc;
        ks[i*65 + sl] = k[gin] * fc;
    }
    __syncthreads();
    float* Qo = g_Qp + (size_t)((b*HH + h)*DH)*SS + st*64;
    float* Ko = g_Kp + (size_t)((b*HH + h)*DH)*2*SS + st*128;
    for (int idx = tid; idx < 64*64; idx += 256) {
        int i = idx >> 6, sl = idx & 63;
        Qo[(size_t)i*SS + sl] = qs[i*65 + sl];
        float kv = ks[i*65 + sl];
        *(float2*)&Ko[(size_t)i*2*SS + 2*sl] = make_float2(kv, kv);
    }
}

// ---------------- flash attention: BM=128, FFMA2, cp.async double buffer ----
// 256 threads as 16x16: thread (ti,tj) owns rows ti*8..+7.
// GEMM1: cols tj*4..+3 (acc m-packed, b from dup-K LDS.128 pairs).
// GEMM2: d = {tj*4..+3, 64+tj*4..+3} (o d-packed, a from dup-Ps LDS.128 pairs).
__global__ __launch_bounds__(256, 1)
void attn_kernel(const float* __restrict__ v, float* __restrict__ out) {
    extern __shared__ float sm[];
    float* QsT = sm;                          // [64][128]              8192 f
    float* Ks0 = QsT + DH*BM;                 // 2 x [64][128 dup]     16384 f
    float* Vs0 = Ks0 + 2*DH*2*BN;             // 2 x [64][128]         16384 f
    float* Ps  = Vs0 + 2*BN*DD;               // [128][PSTR2 dup]      16896 f

    const int qt = blockIdx.x, h = blockIdx.y, b = blockIdx.z;
    const int tid = threadIdx.x;
    const int ti = tid >> 4;         // 0..15
    const int tj = tid & 15;         // 0..15

    const float* Qg  = g_Qp + (size_t)((b*HH + h)*DH)*SS + qt*BM;
    const float* Kg0 = g_Kp + (size_t)((b*HH + h)*DH)*2*SS;
    const float* Vg0 = v + ((size_t)b*SS*HH + h)*DD;

    const uint32_t s_qst = (uint32_t)__cvta_generic_to_shared(QsT);
    const uint32_t s_ks  = (uint32_t)__cvta_generic_to_shared(Ks0);
    const uint32_t s_vs  = (uint32_t)__cvta_generic_to_shared(Vs0);

    // ---- prologue: Q tile + tile 0 of K/V via cp.async ----
    // Q: 2048 float4, 8 per thread
    #pragma unroll
    for (int it = 0; it < 8; it++) {
        int idx4 = tid + it*256;
        int kk = idx4 >> 5, m4 = idx4 & 31;
        cp_async16(s_qst + (uint32_t)idx4*16, Qg + (size_t)kk*SS + m4*4);
    }
    // K tile 0 (dup): 2048 float4, 8 per thread
    #pragma unroll
    for (int it = 0; it < 8; it++) {
        int idx4 = tid + it*256;
        int kk = idx4 >> 5, n4 = idx4 & 31;
        cp_async16(s_ks + (uint32_t)idx4*16, Kg0 + (size_t)kk*2*SS + n4*4);
    }
    // V tile 0: 2048 float4, 8 per thread
    #pragma unroll
    for (int it = 0; it < 8; it++) {
        int idx4 = tid + it*256;
        int r = idx4 >> 5, c4 = idx4 & 31;
        cp_async16(s_vs + (uint32_t)idx4*16, Vg0 + (size_t)r*HH*DD + c4*4);
    }
    cp_commit();

    float mrow[8], lrow[8];   // mrow in base-2 (log2) units
    #pragma unroll
    for (int r = 0; r < 8; r++) { mrow[r] = -INFINITY; lrow[r] = 0.0f; }

    u64 o2[8][4];
    #pragma unroll
    for (int r = 0; r < 8; r++)
        #pragma unroll
        for (int c = 0; c < 4; c++) o2[r][c] = 0ULL;

    int buf = 0;
    for (int kt = 0; kt < SS/BN; ++kt) {
        cp_wait_all();
        __syncthreads();   // tile[buf] ready; prev compute done with tile[buf^1]

        // issue next tile into buf^1 (overlaps with this iteration's compute)
        if (kt + 1 < SS/BN) {
            const float* Kg = Kg0 + (size_t)(kt + 1)*2*BN;
            const float* Vg = Vg0 + (size_t)((kt + 1)*BN)*HH*DD;
            uint32_t ks_dst = s_ks + (uint32_t)(buf ^ 1)*DH*2*BN*4;
            uint32_t vs_dst = s_vs + (uint32_t)(buf ^ 1)*BN*DD*4;
            #pragma unroll
            for (int it = 0; it < 8; it++) {
                int idx4 = tid + it*256;
                int kk = idx4 >> 5, n4 = idx4 & 31;
                cp_async16(ks_dst + (uint32_t)idx4*16, Kg + (size_t)kk*2*SS + n4*4);
            }
            #pragma unroll
            for (int it = 0; it < 8; it++) {
                int idx4 = tid + it*256;
                int r = idx4 >> 5, c4 = idx4 & 31;
                cp_async16(vs_dst + (uint32_t)idx4*16, Vg + (size_t)r*HH*DD + c4*4);
            }
        }
        cp_commit();   // empty group when no issue: wait_group 0 still fine

        const float* KsT = Ks0 + buf*DH*2*BN;
        const float* Vs  = Vs0 + buf*BN*DD;

        // ---- GEMM1: S = Q'K'^T. acc m-packed; b pairs direct from dup-K ----
        u64 acc2[4][4];
        #pragma unroll
        for (int mp = 0; mp < 4; mp++)
            #pragma unroll
            for (int n = 0; n < 4; n++) acc2[mp][n] = 0ULL;

        #pragma unroll 16
        for (int kk = 0; kk < DH; ++kk) {
            ulonglong2 a01 = *(const ulonglong2*)&QsT[(kk << 7) + (ti << 3)];
            ulonglong2 a23 = *(const ulonglong2*)&QsT[(kk << 7) + (ti << 3) + 4];
            ulonglong2 b01 = *(const ulonglong2*)&KsT[(kk << 7) + (tj << 3)];
            ulonglong2 b23 = *(const ulonglong2*)&KsT[(kk << 7) + (tj << 3) + 4];
            ffma2(acc2[0][0], a01.x, b01.x); ffma2(acc2[0][1], a01.x, b01.y);
            ffma2(acc2[0][2], a01.x, b23.x); ffma2(acc2[0][3], a01.x, b23.y);
            ffma2(acc2[1][0], a01.y, b01.x); ffma2(acc2[1][1], a01.y, b01.y);
            ffma2(acc2[1][2], a01.y, b23.x); ffma2(acc2[1][3], a01.y, b23.y);
            ffma2(acc2[2][0], a23.x, b01.x); ffma2(acc2[2][1], a23.x, b01.y);
            ffma2(acc2[2][2], a23.x, b23.x); ffma2(acc2[2][3], a23.x, b23.y);
            ffma2(acc2[3][0], a23.y, b01.x); ffma2(acc2[3][1], a23.y, b01.y);
            ffma2(acc2[3][2], a23.y, b23.x); ffma2(acc2[3][3], a23.y, b23.y);
        }

        // ---- softmax in base-2: logit2 = acc * (log2e/64) ----
        float p[8][4];
        #pragma unroll
        for (int mp = 0; mp < 4; mp++)
            #pragma unroll
            for (int n = 0; n < 4; n++)
                unpack2(acc2[mp][n], p[2*mp][n], p[2*mp + 1][n]);

        const float sc2 = 1.44269504088896340736f / 64.0f;  // log2(e)/64

        float mx[8];
        #pragma unroll
        for (int r = 0; r < 8; r++)
            mx[r] = fmaxf(fmaxf(p[r][0], p[r][1]), fmaxf(p[r][2], p[r][3]));
        #pragma unroll
        for (int st = 1; st < 16; st <<= 1)
            #pragma unroll
            for (int r = 0; r < 8; r++)
                mx[r] = fmaxf(mx[r], __shfl_xor_sync(0xffffffffu, mx[r], st));

        float fr[8];
        #pragma unroll
        for (int r = 0; r < 8; r++) {
            float mn = fmaxf(mrow[r], mx[r]*sc2);
            fr[r] = exp2f(mrow[r] - mn);   // exp2f(-inf)=0 on first tile
            mrow[r] = mn;
        }

        float sr[8];
        #pragma unroll
        for (int r = 0; r < 8; r++) {
            #pragma unroll
            for (int cx = 0; cx < 4; cx++)
                p[r][cx] = exp2f(fmaf(p[r][cx], sc2, -mrow[r]));
            sr[r] = (p[r][0] + p[r][1]) + (p[r][2] + p[r][3]);
            // duplicated store: (p0,p0,p1,p1),(p2,p2,p3,p3)
            float4 w1; w1.x = p[r][0]; w1.y = p[r][0]; w1.z = p[r][1]; w1.w = p[r][1];
            float4 w2; w2.x = p[r][2]; w2.y = p[r][2]; w2.z = p[r][3]; w2.w = p[r][3];
            *(float4*)&Ps[(ti*8 + r)*PSTR2 + tj*8]     = w1;
            *(float4*)&Ps[(ti*8 + r)*PSTR2 + tj*8 + 4] = w2;
        }
        #pragma unroll
        for (int st = 1; st < 16; st <<= 1)
            #pragma unroll
            for (int r = 0; r < 8; r++)
                sr[r] += __shfl_xor_sync(0xffffffffu, sr[r], st);
        #pragma unroll
        for (int r = 0; r < 8; r++) {
            lrow[r] = lrow[r]*fr[r] + sr[r];
            u64 f2 = bcast2(fr[r]);
            #pragma unroll
            for (int c = 0; c < 4; c++) o2[r][c] = mul2(o2[r][c], f2);
        }
        __syncwarp();   // Ps rows ti*8+r written/read by the same 16-lane groups

        // ---- GEMM2: O += P V; a pairs direct from dup-Ps, 2 kk per chunk ----
        #pragma unroll 4
        for (int kc = 0; kc < BN/2; ++kc) {
            u64 pp[8][2];
            #pragma unroll
            for (int r = 0; r < 8; r++) {
                ulonglong2 t = *(const ulonglong2*)&Ps[(ti*8 + r)*PSTR2 + kc*4];
                pp[r][0] = t.x; pp[r][1] = t.y;
            }
            #pragma unroll
            for (int j = 0; j < 2; j++) {
                int kk = kc*2 + j;
                ulonglong2 v0 = *(const ulonglong2*)&Vs[kk*DD + tj*4];
                ulonglong2 v1 = *(const ulonglong2*)&Vs[kk*DD + 64 + tj*4];
                #pragma unroll
                for (int r = 0; r < 8; r++) {
                    ffma2(o2[r][0], pp[r][j], v0.x);
                    ffma2(o2[r][1], pp[r][j], v0.y);
                    ffma2(o2[r][2], pp[r][j], v1.x);
                    ffma2(o2[r][3], pp[r][j], v1.y);
                }
            }
        }
        buf ^= 1;
    }

    // ---- normalize + write out[b,s,h,d]; d = tj*4 and 64+tj*4 ----
    #pragma unroll
    for (int r = 0; r < 8; r++) {
        int srow = qt*BM + ti*8 + r;
        float inv_l = 1.0f / lrow[r];
        float w[8];
        unpack2(o2[r][0], w[0], w[1]); unpack2(o2[r][1], w[2], w[3]);
        unpack2(o2[r][2], w[4], w[5]); unpack2(o2[r][3], w[6], w[7]);
        float* op = out + (((size_t)b*SS + srow)*HH + h)*DD;
        float4 w0, w1;
        w0.x = w[0]*inv_l; w0.y = w[1]*inv_l; w0.z = w[2]*inv_l; w0.w = w[3]*inv_l;
        w1.x = w[4]*inv_l; w1.y = w[5]*inv_l; w1.z = w[6]*inv_l; w1.w = w[7]*inv_l;
        *(float4*)(op + tj*4)      = w0;
        *(float4*)(op + 64 + tj*4) = w1;
    }
}

extern "C" void kernel_launch(void* const* d_in, const int* in_sizes, int n_in,
                              void* d_out, int out_size) {
    const float* q = (const float*)d_in[0];
    const float* k = (const float*)d_in[1];
    const float* v = (const float*)d_in[2];
    float* out = (float*)d_out;

    // 8192 + 16384 + 16384 + 16896 floats = 231424 B (limit 232448)
    const int smem = (DH*BM + 2*DH*2*BN + 2*BN*DD + BM*PSTR2) * (int)sizeof(float);
    cudaFuncSetAttribute(attn_kernel, cudaFuncAttributeMaxDynamicSharedMemorySize, smem);

    init_inv<<<1, 64>>>();
    dim3 pgrid(SS/64, HH, BB);
    prep_qk<<<pgrid, 256>>>(q, k);

    dim3 grid(SS/BM, HH, BB);
    attn_kernel<<<grid, 256, smem>>>(v, out);
}

// round 8
// speedup vs baseline: 1.3781x; 1.3781x over previous
#include <cuda_runtime.h>
#include <math.h>
#include <stdint.h>

#define BB 4
#define SS 2048
#define HH 16
#define DD 128
#define DH 64    // effective qk dim (first half, duplicated in reference)
#define BM 128
#define BN 64
#define PSTR 68

typedef unsigned long long u64;

// Scratch (no allocations allowed): k-major preprocessed Q', K'.
__device__ float g_Qp[BB*HH*DH*SS];   // [b,h,kdim,s]  33.5 MB
__device__ float g_Kp[BB*HH*DH*SS];   // [b,h,kdim,s]  33.5 MB
__device__ float g_inv[DH];

// ---------------- packed f32x2 helpers (sm_103a) ----------------
__device__ __forceinline__ u64 bcast2(float x) {
    u64 r;
    asm("mov.b64 %0, {%1, %1};" : "=l"(r) : "f"(x));
    return r;
}
__device__ __forceinline__ void ffma2(u64& d, u64 a, u64 b) {
    asm("fma.rn.f32x2 %0, %1, %2, %3;" : "=l"(d) : "l"(a), "l"(b), "l"(d));
}
__device__ __forceinline__ u64 mul2(u64 a, u64 b) {
    u64 d;
    asm("mul.rn.f32x2 %0, %1, %2;" : "=l"(d) : "l"(a), "l"(b));
    return d;
}
__device__ __forceinline__ void unpack2(u64 v, float& lo, float& hi) {
    asm("mov.b64 {%0, %1}, %2;" : "=f"(lo), "=f"(hi) : "l"(v));
}

// ---------------- fast exp2: FMA+ALU pipes only, no MUFU ----------------
// Valid for x <= 0 (softmax exponents). Clamps below -125 -> ~0.
// Error ~2e-6 relative (degree-5 Taylor of 2^f on [-0.5, 0.5]).
__device__ __forceinline__ float fexp2(float x) {
    x = fmaxf(x, -125.0f);                          // FMNMX (alu pipe)
    float t  = __fadd_rn(x, 12582912.0f);           // 1.5*2^23: RN to int
    int   n  = __float_as_int(t) - 0x4B400000;      // n = round(x)  (alu)
    float nf = __fsub_rn(t, 12582912.0f);
    float f  = __fsub_rn(x, nf);                    // f in [-0.5, 0.5]
    float p  = 1.33335581e-3f;
    p = fmaf(p, f, 9.61812911e-3f);
    p = fmaf(p, f, 5.55041087e-2f);
    p = fmaf(p, f, 2.40226507e-1f);
    p = fmaf(p, f, 6.93147181e-1f);
    p = fmaf(p, f, 1.0f);                           // p = 2^f in [0.707, 1.415]
    return __int_as_float(__float_as_int(p) + (n << 23));   // * 2^n (alu)
}

// ---------------- cp.async helpers ----------------
__device__ __forceinline__ void cp_async16(uint32_t saddr, const void* gptr) {
    asm volatile("cp.async.cg.shared.global [%0], [%1], 16;"
                 :: "r"(saddr), "l"(gptr));
}
__device__ __forceinline__ void cp_commit() {
    asm volatile("cp.async.commit_group;");
}
__device__ __forceinline__ void cp_wait_all() {
    asm volatile("cp.async.wait_group 0;");
}

// ---------------- prep ----------------
__global__ void init_inv() {
    int i = threadIdx.x;
    g_inv[i] = (float)exp(-(double)i * (9.210340371976184 / 64.0)); // ln(1e4)/64
}

// Tiled transpose: q,k [b,s,h,128] (first 64 dims) * fc -> [b,h,64,s]
__global__ void prep_qk(const float* __restrict__ q, const float* __restrict__ k) {
    __shared__ float qs[64*65];
    __shared__ float ks[64*65];
    const int st = blockIdx.x, h = blockIdx.y, b = blockIdx.z;
    const int tid = threadIdx.x;
    for (int idx = tid; idx < 64*64; idx += 256) {
        int sl = idx >> 6, i = idx & 63;
        int s = st*64 + sl;
        float fc = 2.0f * ((float)s * g_inv[i]);
        size_t gin = ((size_t)(b*SS + s)*HH + h)*DD + i;
        qs[i*65 + sl] = q[gin] * fc;
        ks[i*65 + sl] = k[gin] * fc;
    }
    __syncthreads();
    float* Qo = g_Qp + (size_t)((b*HH + h)*DH)*SS + st*64;
    float* Ko = g_Kp + (size_t)((b*HH + h)*DH)*SS + st*64;
    for (int idx = tid; idx < 64*64; idx += 256) {
        int i = idx >> 6, sl = idx & 63;
        Qo[(size_t)i*SS + sl] = qs[i*65 + sl];
        Ko[(size_t)i*SS + sl] = ks[i*65 + sl];
    }
}

// ---------------- flash attention: BM=128, FFMA2, cp.async double buffer ----
// 256 threads as 16x16: thread (ti,tj) owns rows ti*8..+7.
// GEMM1: cols tj*4..+3 (acc m-packed). GEMM2: d = {tj*4..+3, 64+tj*4..+3}.
__global__ __launch_bounds__(256, 1)
void attn_kernel(const float* __restrict__ v, float* __restrict__ out) {
    extern __shared__ float sm[];
    float* QsT = sm;                          // [64][128]              8192
    float* Ks0 = QsT + DH*BM;                 // 2 x [64][64]           8192
    float* Vs0 = Ks0 + 2*DH*BN;               // 2 x [64][128]         16384
    float* Ps  = Vs0 + 2*BN*DD;               // [128][PSTR]            8704

    const int qt = blockIdx.x, h = blockIdx.y, b = blockIdx.z;
    const int tid = threadIdx.x;
    const int ti = tid >> 4;         // 0..15
    const int tj = tid & 15;         // 0..15

    const float* Qg  = g_Qp + (size_t)((b*HH + h)*DH)*SS + qt*BM;
    const float* Kg0 = g_Kp + (size_t)((b*HH + h)*DH)*SS;
    const float* Vg0 = v + ((size_t)b*SS*HH + h)*DD;

    const uint32_t s_qst = (uint32_t)__cvta_generic_to_shared(QsT);
    const uint32_t s_ks  = (uint32_t)__cvta_generic_to_shared(Ks0);
    const uint32_t s_vs  = (uint32_t)__cvta_generic_to_shared(Vs0);

    // ---- prologue: Q tile + tile 0 of K/V via cp.async ----
    #pragma unroll
    for (int it = 0; it < 8; it++) {
        int idx4 = tid + it*256;
        int kk = idx4 >> 5, m4 = idx4 & 31;
        cp_async16(s_qst + (uint32_t)idx4*16, Qg + (size_t)kk*SS + m4*4);
    }
    #pragma unroll
    for (int it = 0; it < 4; it++) {
        int idx4 = tid + it*256;
        int kk = idx4 >> 4, n4 = idx4 & 15;
        cp_async16(s_ks + (uint32_t)idx4*16, Kg0 + (size_t)kk*SS + n4*4);
    }
    #pragma unroll
    for (int it = 0; it < 8; it++) {
        int idx4 = tid + it*256;
        int r = idx4 >> 5, c4 = idx4 & 31;
        cp_async16(s_vs + (uint32_t)idx4*16, Vg0 + (size_t)r*HH*DD + c4*4);
    }
    cp_commit();

    float mrow[8], lrow[8];   // mrow in base-2 (log2) units
    #pragma unroll
    for (int r = 0; r < 8; r++) { mrow[r] = -INFINITY; lrow[r] = 0.0f; }

    u64 o2[8][4];
    #pragma unroll
    for (int r = 0; r < 8; r++)
        #pragma unroll
        for (int c = 0; c < 4; c++) o2[r][c] = 0ULL;

    int buf = 0;
    for (int kt = 0; kt < SS/BN; ++kt) {
        cp_wait_all();
        __syncthreads();   // tile[buf] ready; prev compute done with tile[buf^1]

        // issue next tile into buf^1 (overlaps with this iteration's compute)
        if (kt + 1 < SS/BN) {
            const float* Kg = Kg0 + (kt + 1)*BN;
            const float* Vg = Vg0 + (size_t)((kt + 1)*BN)*HH*DD;
            uint32_t ks_dst = s_ks + (uint32_t)(buf ^ 1)*DH*BN*4;
            uint32_t vs_dst = s_vs + (uint32_t)(buf ^ 1)*BN*DD*4;
            #pragma unroll
            for (int it = 0; it < 4; it++) {
                int idx4 = tid + it*256;
                int kk = idx4 >> 4, n4 = idx4 & 15;
                cp_async16(ks_dst + (uint32_t)idx4*16, Kg + (size_t)kk*SS + n4*4);
            }
            #pragma unroll
            for (int it = 0; it < 8; it++) {
                int idx4 = tid + it*256;
                int r = idx4 >> 5, c4 = idx4 & 31;
                cp_async16(vs_dst + (uint32_t)idx4*16, Vg + (size_t)r*HH*DD + c4*4);
            }
        }
        cp_commit();   // empty group when no issue: wait_group 0 still fine

        const float* KsT = Ks0 + buf*DH*BN;
        const float* Vs  = Vs0 + buf*BN*DD;

        // ---- GEMM1: S = Q'K'^T. acc m-packed: acc2[mp][n] = rows {2mp,2mp+1} ----
        u64 acc2[4][4];
        #pragma unroll
        for (int mp = 0; mp < 4; mp++)
            #pragma unroll
            for (int n = 0; n < 4; n++) acc2[mp][n] = 0ULL;

        #pragma unroll 16
        for (int kk = 0; kk < DH; ++kk) {
            ulonglong2 a01 = *(const ulonglong2*)&QsT[(kk << 7) + (ti << 3)];
            ulonglong2 a23 = *(const ulonglong2*)&QsT[(kk << 7) + (ti << 3) + 4];
            float4 b4 = *(const float4*)&KsT[(kk << 6) + (tj << 2)];
            u64 b0 = bcast2(b4.x), b1 = bcast2(b4.y);
            u64 b2 = bcast2(b4.z), b3 = bcast2(b4.w);
            ffma2(acc2[0][0], a01.x, b0); ffma2(acc2[0][1], a01.x, b1);
            ffma2(acc2[0][2], a01.x, b2); ffma2(acc2[0][3], a01.x, b3);
            ffma2(acc2[1][0], a01.y, b0); ffma2(acc2[1][1], a01.y, b1);
            ffma2(acc2[1][2], a01.y, b2); ffma2(acc2[1][3], a01.y, b3);
            ffma2(acc2[2][0], a23.x, b0); ffma2(acc2[2][1], a23.x, b1);
            ffma2(acc2[2][2], a23.x, b2); ffma2(acc2[2][3], a23.x, b3);
            ffma2(acc2[3][0], a23.y, b0); ffma2(acc2[3][1], a23.y, b1);
            ffma2(acc2[3][2], a23.y, b2); ffma2(acc2[3][3], a23.y, b3);
        }

        // ---- softmax in base-2: logit2 = acc * (log2e/64); exp on FMA/ALU pipes ----
        float p[8][4];
        #pragma unroll
        for (int mp = 0; mp < 4; mp++)
            #pragma unroll
            for (int n = 0; n < 4; n++)
                unpack2(acc2[mp][n], p[2*mp][n], p[2*mp + 1][n]);

        const float sc2 = 1.44269504088896340736f / 64.0f;  // log2(e)/64

        float mx[8];
        #pragma unroll
        for (int r = 0; r < 8; r++)
            mx[r] = fmaxf(fmaxf(p[r][0], p[r][1]), fmaxf(p[r][2], p[r][3]));
        #pragma unroll
        for (int st = 1; st < 16; st <<= 1)
            #pragma unroll
            for (int r = 0; r < 8; r++)
                mx[r] = fmaxf(mx[r], __shfl_xor_sync(0xffffffffu, mx[r], st));

        float fr[8];
        #pragma unroll
        for (int r = 0; r < 8; r++) {
            float mn = fmaxf(mrow[r], mx[r]*sc2);
            fr[r] = fexp2(mrow[r] - mn);   // -inf clamps to 2^-125 ~ 0 on first tile
            mrow[r] = mn;
        }

        float sr[8];
        #pragma unroll
        for (int r = 0; r < 8; r++) {
            #pragma unroll
            for (int cx = 0; cx < 4; cx++)
                p[r][cx] = fexp2(fmaf(p[r][cx], sc2, -mrow[r]));
            sr[r] = (p[r][0] + p[r][1]) + (p[r][2] + p[r][3]);
            float4 pw; pw.x = p[r][0]; pw.y = p[r][1]; pw.z = p[r][2]; pw.w = p[r][3];
            *(float4*)&Ps[(ti*8 + r)*PSTR + tj*4] = pw;
        }
        #pragma unroll
        for (int st = 1; st < 16; st <<= 1)
            #pragma unroll
            for (int r = 0; r < 8; r++)
                sr[r] += __shfl_xor_sync(0xffffffffu, sr[r], st);
        #pragma unroll
        for (int r = 0; r < 8; r++) {
            lrow[r] = lrow[r]*fr[r] + sr[r];
            u64 f2 = bcast2(fr[r]);
            #pragma unroll
            for (int c = 0; c < 4; c++) o2[r][c] = mul2(o2[r][c], f2);
        }
        __syncwarp();   // Ps rows ti*8+r written/read by the same 16-lane groups

        // ---- GEMM2: O += P V ----
        #pragma unroll 2
        for (int kc = 0; kc < BN/4; ++kc) {
            float4 pr[8];
            #pragma unroll
            for (int r = 0; r < 8; r++)
                pr[r] = *(const float4*)&Ps[(ti*8 + r)*PSTR + kc*4];
            #pragma unroll
            for (int j = 0; j < 4; j++) {
                int kk = kc*4 + j;
                ulonglong2 v0 = *(const ulonglong2*)&Vs[kk*DD + tj*4];
                ulonglong2 v1 = *(const ulonglong2*)&Vs[kk*DD + 64 + tj*4];
                #pragma unroll
                for (int r = 0; r < 8; r++) {
                    float pv = (j == 0) ? pr[r].x : (j == 1) ? pr[r].y
                             : (j == 2) ? pr[r].z : pr[r].w;
                    u64 a2 = bcast2(pv);
                    ffma2(o2[r][0], a2, v0.x);
                    ffma2(o2[r][1], a2, v0.y);
                    ffma2(o2[r][2], a2, v1.x);
                    ffma2(o2[r][3], a2, v1.y);
                }
            }
        }
        buf ^= 1;
    }

    // ---- normalize + write out[b,s,h,d]; d = tj*4 and 64+tj*4 ----
    #pragma unroll
    for (int r = 0; r < 8; r++) {
        int srow = qt*BM + ti*8 + r;
        float inv_l = 1.0f / lrow[r];
        float w[8];
        unpack2(o2[r][0], w[0], w[1]); unpack2(o2[r][1], w[2], w[3]);
        unpack2(o2[r][2], w[4], w[5]); unpack2(o2[r][3], w[6], w[7]);
        float* op = out + (((size_t)b*SS + srow)*HH + h)*DD;
        float4 w0, w1;
        w0.x = w[0]*inv_l; w0.y = w[1]*inv_l; w0.z = w[2]*inv_l; w0.w = w[3]*inv_l;
        w1.x = w[4]*inv_l; w1.y = w[5]*inv_l; w1.z = w[6]*inv_l; w1.w = w[7]*inv_l;
        *(float4*)(op + tj*4)      = w0;
        *(float4*)(op + 64 + tj*4) = w1;
    }
}

extern "C" void kernel_launch(void* const* d_in, const int* in_sizes, int n_in,
                              void* d_out, int out_size) {
    const float* q = (const float*)d_in[0];
    const float* k = (const float*)d_in[1];
    const float* v = (const float*)d_in[2];
    float* out = (float*)d_out;

    const int smem = (DH*BM + 2*DH*BN + 2*BN*DD + BM*PSTR) * (int)sizeof(float); // 165888 B
    cudaFuncSetAttribute(attn_kernel, cudaFuncAttributeMaxDynamicSharedMemorySize, smem);

    init_inv<<<1, 64>>>();
    dim3 pgrid(SS/64, HH, BB);
    prep_qk<<<pgrid, 256>>>(q, k);

    dim3 grid(SS/BM, HH, BB);
    attn_kernel<<<grid, 256, smem>>>(v, out);
}

// round 10
// speedup vs baseline: 2.1617x; 1.5686x over previous
#include <cuda_runtime.h>
#include <cuda_bf16.h>
#include <math.h>
#include <stdint.h>

#define BB 4
#define SS 2048
#define HH 16
#define DD 128
#define DH 64    // effective qk dim (first half, duplicated in reference)
#define BM 128
#define BN 64

typedef unsigned long long u64;

// ---- scratch (no allocs allowed) ----
__device__ float g_Qp[BB*HH*DH*SS];                  // [b,h,kdim,s]  33.5 MB
__device__ float g_Kp[BB*HH*DH*SS];                  // [b,h,kdim,s]  33.5 MB
__device__ __nv_bfloat16 g_Vhi[(size_t)BB*HH*SS*DD]; // [b,h,s,d]     33.5 MB
__device__ __nv_bfloat16 g_Vlo[(size_t)BB*HH*SS*DD]; // [b,h,s,d]     33.5 MB
__device__ float g_inv[DH];

// ---- smem layout (bytes) ----
#define OFF_QST 0           // fp32 Q  [64 kdim][128 m]        32768
#define OFF_KS  32768       // fp32 K  2 x [64 kdim][64 n]     32768
#define OFF_VHI 65536       // bf16 V hi 2 x [64 k][128 d]     34816 (row 272B)
#define OFF_VLO 100352      // bf16 V lo                       34816
#define OFF_PHI 135168      // bf16 P hi [128 m][64 k]         18432 (row 144B)
#define OFF_PLO 153600      // bf16 P lo                       18432
#define OFF_F   172032      // float f[128]
#define OFF_L   172544      // float l[128]
#define SMEM_TOTAL 173056
#define VROWB 272           // 272 ≡ 4 words mod 32 banks -> conflict-free ldmatrix
#define VTILE 17408         // 64 * 272
#define PROWB 144           // 144 ≡ 4 words mod 32

// ---------------- packed f32x2 helpers (GEMM1) ----------------
__device__ __forceinline__ u64 bcast2(float x) {
    u64 r; asm("mov.b64 %0, {%1, %1};" : "=l"(r) : "f"(x)); return r;
}
__device__ __forceinline__ void ffma2(u64& d, u64 a, u64 b) {
    asm("fma.rn.f32x2 %0, %1, %2, %3;" : "=l"(d) : "l"(a), "l"(b), "l"(d));
}
__device__ __forceinline__ void unpack2(u64 v, float& lo, float& hi) {
    asm("mov.b64 {%0, %1}, %2;" : "=f"(lo), "=f"(hi) : "l"(v));
}

// ---------------- cp.async ----------------
__device__ __forceinline__ void cp_async16(uint32_t saddr, const void* gptr) {
    asm volatile("cp.async.cg.shared.global [%0], [%1], 16;" :: "r"(saddr), "l"(gptr));
}
__device__ __forceinline__ void cp_commit() { asm volatile("cp.async.commit_group;"); }
__device__ __forceinline__ void cp_wait_all() { asm volatile("cp.async.wait_group 0;"); }

// ---------------- tensor core: ldmatrix + mma.sync (base PTX, sm_80+) ----------------
__device__ __forceinline__ void ldmx4(uint32_t* r, uint32_t a) {
    asm volatile("ldmatrix.sync.aligned.m8n8.x4.shared.b16 {%0,%1,%2,%3}, [%4];"
        : "=r"(r[0]), "=r"(r[1]), "=r"(r[2]), "=r"(r[3]) : "r"(a));
}
__device__ __forceinline__ void ldmx4t(uint32_t* r, uint32_t a) {
    asm volatile("ldmatrix.sync.aligned.m8n8.x4.trans.shared.b16 {%0,%1,%2,%3}, [%4];"
        : "=r"(r[0]), "=r"(r[1]), "=r"(r[2]), "=r"(r[3]) : "r"(a));
}
__device__ __forceinline__ void mma16816(float* c, const uint32_t* a, const uint32_t* b) {
    asm volatile("mma.sync.aligned.m16n8k16.row.col.f32.bf16.bf16.f32 "
        "{%0,%1,%2,%3}, {%4,%5,%6,%7}, {%8,%9}, {%0,%1,%2,%3};"
        : "+f"(c[0]), "+f"(c[1]), "+f"(c[2]), "+f"(c[3])
        : "r"(a[0]), "r"(a[1]), "r"(a[2]), "r"(a[3]), "r"(b[0]), "r"(b[1]));
}

// ---------------- prep ----------------
__global__ void init_inv() {
    int i = threadIdx.x;
    g_inv[i] = (float)exp(-(double)i * (9.210340371976184 / 64.0)); // ln(1e4)/64
}

// q,k [b,s,h,128] (first 64 dims) * fc -> [b,h,64,s]
__global__ void prep_qk(const float* __restrict__ q, const float* __restrict__ k) {
    __shared__ float qs[64*65];
    __shared__ float ks[64*65];
    const int st = blockIdx.x, h = blockIdx.y, b = blockIdx.z;
    const int tid = threadIdx.x;
    for (int idx = tid; idx < 64*64; idx += 256) {
        int sl = idx >> 6, i = idx & 63;
        int s = st*64 + sl;
        float fc = 2.0f * ((float)s * g_inv[i]);
        size_t gin = ((size_t)(b*SS + s)*HH + h)*DD + i;
        qs[i*65 + sl] = q[gin] * fc;
        ks[i*65 + sl] = k[gin] * fc;
    }
    __syncthreads();
    float* Qo = g_Qp + (size_t)((b*HH + h)*DH)*SS + st*64;
    float* Ko = g_Kp + (size_t)((b*HH + h)*DH)*SS + st*64;
    for (int idx = tid; idx < 64*64; idx += 256) {
        int i = idx >> 6, sl = idx & 63;
        Qo[(size_t)i*SS + sl] = qs[i*65 + sl];
        Ko[(size_t)i*SS + sl] = ks[i*65 + sl];
    }
}

// v [b,s,h,128] -> bf16 hi/lo [b,h,s,128] (head transpose only, d stays contiguous)
__global__ void prep_v(const float* __restrict__ v) {
    const int st = blockIdx.x, h = blockIdx.y, b = blockIdx.z;
    const int tid = threadIdx.x;
    for (int idx = tid; idx < 64*32; idx += 256) {     // 64 s-rows x 32 float4
        int s = idx >> 5, d4 = idx & 31;
        float4 x = *(const float4*)&v[((size_t)(b*SS + st*64 + s)*HH + h)*DD + d4*4];
        __nv_bfloat16 h0 = __float2bfloat16(x.x), h1 = __float2bfloat16(x.y);
        __nv_bfloat16 h2 = __float2bfloat16(x.z), h3 = __float2bfloat16(x.w);
        __nv_bfloat16 l0 = __float2bfloat16(x.x - __bfloat162float(h0));
        __nv_bfloat16 l1 = __float2bfloat16(x.y - __bfloat162float(h1));
        __nv_bfloat16 l2 = __float2bfloat16(x.z - __bfloat162float(h2));
        __nv_bfloat16 l3 = __float2bfloat16(x.w - __bfloat162float(h3));
        size_t o = ((size_t)(b*HH + h)*SS + st*64 + s)*DD + d4*4;
        __nv_bfloat162* ph = (__nv_bfloat162*)(g_Vhi + o);
        __nv_bfloat162* pl = (__nv_bfloat162*)(g_Vlo + o);
        __nv_bfloat162 a; a.x = h0; a.y = h1; ph[0] = a;
        a.x = h2; a.y = h3; ph[1] = a;
        a.x = l0; a.y = l1; pl[0] = a;
        a.x = l2; a.y = l3; pl[1] = a;
    }
}

// ---------------- flash attention: FFMA2 GEMM1 + HMMA (mma.sync) GEMM2 ----------------
// 256 threads / 8 warps. GEMM1+softmax: thread (ti,tj) 16x16 owns rows ti*8..+7.
// GEMM2: warp w owns rows w*16..+15 (same rows -> P handoff is warp-private).
__global__ __launch_bounds__(256, 1)
void attn_kernel(float* __restrict__ out) {
    extern __shared__ char smem[];
    const uint32_t sbase = (uint32_t)__cvta_generic_to_shared(smem);
    float* QsT  = (float*)(smem + OFF_QST);
    float* Ks0  = (float*)(smem + OFF_KS);
    float* fptr = (float*)(smem + OFF_F);
    float* lptr = (float*)(smem + OFF_L);

    const int qt = blockIdx.x, h = blockIdx.y, b = blockIdx.z;
    const int tid = threadIdx.x;
    const int wid = tid >> 5, lane = tid & 31;
    const int ti = tid >> 4, tj = tid & 15;
    const int warp_m = wid * 16;

    const float* Qg  = g_Qp + (size_t)((b*HH + h)*DH)*SS + qt*BM;
    const float* Kg0 = g_Kp + (size_t)((b*HH + h)*DH)*SS;
    const __nv_bfloat16* Vh0 = g_Vhi + (size_t)(b*HH + h)*SS*DD;
    const __nv_bfloat16* Vl0 = g_Vlo + (size_t)(b*HH + h)*SS*DD;

    // ---- prologue: Q + tile0 K/Vhi/Vlo via cp.async ----
    #pragma unroll
    for (int it = 0; it < 8; it++) {
        int idx4 = tid + it*256;
        int kk = idx4 >> 5, m4 = idx4 & 31;
        cp_async16(sbase + OFF_QST + (uint32_t)idx4*16, Qg + (size_t)kk*SS + m4*4);
    }
    #pragma unroll
    for (int it = 0; it < 4; it++) {
        int idx4 = tid + it*256;
        int kk = idx4 >> 4, n4 = idx4 & 15;
        cp_async16(sbase + OFF_KS + (uint32_t)idx4*16, Kg0 + (size_t)kk*SS + n4*4);
    }
    #pragma unroll
    for (int it = 0; it < 4; it++) {     // 64 rows x 16 chunks of 16B per split
        int idx = tid + it*256;
        int row = idx >> 4, c = idx & 15;
        cp_async16(sbase + OFF_VHI + (uint32_t)row*VROWB + c*16, Vh0 + (size_t)row*DD + c*8);
        cp_async16(sbase + OFF_VLO + (uint32_t)row*VROWB + c*16, Vl0 + (size_t)row*DD + c*8);
    }
    cp_commit();

    float mrow[8], lrow[8];   // base-2 units
    #pragma unroll
    for (int r = 0; r < 8; r++) { mrow[r] = -INFINITY; lrow[r] = 0.0f; }

    float c[64];              // 16 n-tiles x 4 (mma C frags), rows warp_m+(lane>>2), +8
    #pragma unroll
    for (int i = 0; i < 64; i++) c[i] = 0.0f;

    int buf = 0;
    for (int kt = 0; kt < SS/BN; ++kt) {
        cp_wait_all();
        __syncthreads();   // K/V tile[buf] ready; all warps done with tile[buf^1]

        if (kt + 1 < SS/BN) {
            const float* Kg = Kg0 + (kt + 1)*BN;
            const __nv_bfloat16* Vh = Vh0 + (size_t)(kt + 1)*BN*DD;
            const __nv_bfloat16* Vl = Vl0 + (size_t)(kt + 1)*BN*DD;
            uint32_t kd = sbase + OFF_KS + (uint32_t)(buf ^ 1)*DH*BN*4;
            uint32_t vh = sbase + OFF_VHI + (uint32_t)(buf ^ 1)*VTILE;
            uint32_t vl = sbase + OFF_VLO + (uint32_t)(buf ^ 1)*VTILE;
            #pragma unroll
            for (int it = 0; it < 4; it++) {
                int idx4 = tid + it*256;
                int kk = idx4 >> 4, n4 = idx4 & 15;
                cp_async16(kd + (uint32_t)idx4*16, Kg + (size_t)kk*SS + n4*4);
            }
            #pragma unroll
            for (int it = 0; it < 4; it++) {
                int idx = tid + it*256;
                int row = idx >> 4, cc = idx & 15;
                cp_async16(vh + (uint32_t)row*VROWB + cc*16, Vh + (size_t)row*DD + cc*8);
                cp_async16(vl + (uint32_t)row*VROWB + cc*16, Vl + (size_t)row*DD + cc*8);
            }
        }
        cp_commit();

        const float* KsT = Ks0 + buf*DH*BN;

        // ---- GEMM1 (fp32 FFMA2, unchanged numerics) ----
        u64 acc2[4][4];
        #pragma unroll
        for (int mp = 0; mp < 4; mp++)
            #pragma unroll
            for (int n = 0; n < 4; n++) acc2[mp][n] = 0ULL;

        #pragma unroll 16
        for (int kk = 0; kk < DH; ++kk) {
            ulonglong2 a01 = *(const ulonglong2*)&QsT[(kk << 7) + (ti << 3)];
            ulonglong2 a23 = *(const ulonglong2*)&QsT[(kk << 7) + (ti << 3) + 4];
            float4 b4 = *(const float4*)&KsT[(kk << 6) + (tj << 2)];
            u64 b0 = bcast2(b4.x), b1 = bcast2(b4.y);
            u64 b2 = bcast2(b4.z), b3 = bcast2(b4.w);
            ffma2(acc2[0][0], a01.x, b0); ffma2(acc2[0][1], a01.x, b1);
            ffma2(acc2[0][2], a01.x, b2); ffma2(acc2[0][3], a01.x, b3);
            ffma2(acc2[1][0], a01.y, b0); ffma2(acc2[1][1], a01.y, b1);
            ffma2(acc2[1][2], a01.y, b2); ffma2(acc2[1][3], a01.y, b3);
            ffma2(acc2[2][0], a23.x, b0); ffma2(acc2[2][1], a23.x, b1);
            ffma2(acc2[2][2], a23.x, b2); ffma2(acc2[2][3], a23.x, b3);
            ffma2(acc2[3][0], a23.y, b0); ffma2(acc2[3][1], a23.y, b1);
            ffma2(acc2[3][2], a23.y, b2); ffma2(acc2[3][3], a23.y, b3);
        }

        // ---- softmax (base-2) + bf16 hi/lo P stores ----
        float p[8][4];
        #pragma unroll
        for (int mp = 0; mp < 4; mp++)
            #pragma unroll
            for (int n = 0; n < 4; n++)
                unpack2(acc2[mp][n], p[2*mp][n], p[2*mp + 1][n]);

        const float sc2 = 1.44269504088896340736f / 64.0f;  // log2(e)/64

        float mx[8];
        #pragma unroll
        for (int r = 0; r < 8; r++)
            mx[r] = fmaxf(fmaxf(p[r][0], p[r][1]), fmaxf(p[r][2], p[r][3]));
        #pragma unroll
        for (int st = 1; st < 16; st <<= 1)
            #pragma unroll
            for (int r = 0; r < 8; r++)
                mx[r] = fmaxf(mx[r], __shfl_xor_sync(0xffffffffu, mx[r], st));

        float fr[8];
        #pragma unroll
        for (int r = 0; r < 8; r++) {
            float mn = fmaxf(mrow[r], mx[r]*sc2);
            fr[r] = exp2f(mrow[r] - mn);   // 0 on first tile
            mrow[r] = mn;
        }

        float sr[8];
        #pragma unroll
        for (int r = 0; r < 8; r++) {
            #pragma unroll
            for (int cx = 0; cx < 4; cx++)
                p[r][cx] = exp2f(fmaf(p[r][cx], sc2, -mrow[r]));
            sr[r] = (p[r][0] + p[r][1]) + (p[r][2] + p[r][3]);

            int rr = ti*8 + r;
            __nv_bfloat16 h0 = __float2bfloat16(p[r][0]), h1 = __float2bfloat16(p[r][1]);
            __nv_bfloat16 h2 = __float2bfloat16(p[r][2]), h3 = __float2bfloat16(p[r][3]);
            __nv_bfloat162 hh01; hh01.x = h0; hh01.y = h1;
            __nv_bfloat162 hh23; hh23.x = h2; hh23.y = h3;
            __nv_bfloat162 ll01, ll23;
            ll01.x = __float2bfloat16(p[r][0] - __bfloat162float(h0));
            ll01.y = __float2bfloat16(p[r][1] - __bfloat162float(h1));
            ll23.x = __float2bfloat16(p[r][2] - __bfloat162float(h2));
            ll23.y = __float2bfloat16(p[r][3] - __bfloat162float(h3));
            *(uint2*)(smem + OFF_PHI + rr*PROWB + tj*8) =
                make_uint2(*(uint32_t*)&hh01, *(uint32_t*)&hh23);
            *(uint2*)(smem + OFF_PLO + rr*PROWB + tj*8) =
                make_uint2(*(uint32_t*)&ll01, *(uint32_t*)&ll23);
            if (tj == 0) fptr[rr] = fr[r];
        }
        #pragma unroll
        for (int st = 1; st < 16; st <<= 1)
            #pragma unroll
            for (int r = 0; r < 8; r++)
                sr[r] += __shfl_xor_sync(0xffffffffu, sr[r], st);
        #pragma unroll
        for (int r = 0; r < 8; r++)
            lrow[r] = lrow[r]*fr[r] + sr[r];

        __syncwarp();   // P rows warp_m..+15 and fptr are warp-private

        // ---- GEMM2 on tensor pipe: C = C*f + Ph*Vh + Ph*Vl + Pl*Vh ----
        {
            float f0 = fptr[warp_m + (lane >> 2)];
            float f1 = fptr[warp_m + (lane >> 2) + 8];
            #pragma unroll
            for (int nt = 0; nt < 16; nt++) {
                c[nt*4 + 0] *= f0; c[nt*4 + 1] *= f0;
                c[nt*4 + 2] *= f1; c[nt*4 + 3] *= f1;
            }
            uint32_t pa = sbase + OFF_PHI + (uint32_t)(warp_m + (lane & 15))*PROWB
                        + ((lane >> 4) << 4);
            uint32_t pl = pa + (OFF_PLO - OFF_PHI);
            uint32_t vb = sbase + OFF_VHI + (uint32_t)buf*VTILE
                        + (uint32_t)(lane & 15)*VROWB + ((lane >> 4) << 4);
            uint32_t vl = vb + (OFF_VLO - OFF_VHI);
            #pragma unroll
            for (int ks = 0; ks < 4; ks++) {
                uint32_t ahi[4], alo[4];
                ldmx4(ahi, pa + ks*32);
                ldmx4(alo, pl + ks*32);
                uint32_t ko = (uint32_t)(ks*16)*VROWB;
                #pragma unroll
                for (int nb = 0; nb < 8; nb++) {
                    uint32_t bh[4], bl[4];
                    ldmx4t(bh, vb + ko + nb*32);
                    ldmx4t(bl, vl + ko + nb*32);
                    mma16816(&c[(2*nb)*4],     ahi, bh);
                    mma16816(&c[(2*nb)*4],     ahi, bl);
                    mma16816(&c[(2*nb)*4],     alo, bh);
                    mma16816(&c[(2*nb + 1)*4], ahi, bh + 2);
                    mma16816(&c[(2*nb + 1)*4], ahi, bl + 2);
                    mma16816(&c[(2*nb + 1)*4], alo, bh + 2);
                }
            }
        }
        buf ^= 1;
    }

    // ---- epilogue: normalize + store ----
    if (tj == 0) {
        #pragma unroll
        for (int r = 0; r < 8; r++) lptr[ti*8 + r] = lrow[r];
    }
    __syncwarp();
    {
        float il0 = 1.0f / lptr[warp_m + (lane >> 2)];
        float il1 = 1.0f / lptr[warp_m + (lane >> 2) + 8];
        int r0 = qt*BM + warp_m + (lane >> 2);
        float* op0 = out + (((size_t)b*SS + r0)*HH + h)*DD + (lane & 3)*2;
        float* op1 = op0 + (size_t)8*HH*DD;   // row+8 -> s+8
        #pragma unroll
        for (int nt = 0; nt < 16; nt++) {
            *(float2*)(op0 + nt*8) = make_float2(c[nt*4 + 0]*il0, c[nt*4 + 1]*il0);
            *(float2*)(op1 + nt*8) = make_float2(c[nt*4 + 2]*il1, c[nt*4 + 3]*il1);
        }
    }
}

extern "C" void kernel_launch(void* const* d_in, const int* in_sizes, int n_in,
                              void* d_out, int out_size) {
    const float* q = (const float*)d_in[0];
    const float* k = (const float*)d_in[1];
    const float* v = (const float*)d_in[2];
    float* out = (float*)d_out;

    cudaFuncSetAttribute(attn_kernel, cudaFuncAttributeMaxDynamicSharedMemorySize, SMEM_TOTAL);

    init_inv<<<1, 64>>>();
    dim3 pgrid(SS/64, HH, BB);
    prep_qk<<<pgrid, 256>>>(q, k);
    prep_v<<<pgrid, 256>>>(v);

    dim3 grid(SS/BM, HH, BB);
    attn_kernel<<<grid, 256, SMEM_TOTAL>>>(out);
}

// round 11
// speedup vs baseline: 2.2771x; 1.0534x over previous
#include <cuda_runtime.h>
#include <cuda_bf16.h>
#include <math.h>
#include <stdint.h>

#define BB 4
#define SS 2048
#define HH 16
#define DD 128
#define DH 64    // effective qk dim (first half, duplicated in reference)
#define BM 128
#define BN 64

typedef unsigned long long u64;

// ---- scratch (no allocs allowed) ----
__device__ float g_Qp[BB*HH*DH*SS];                  // [b,h,kdim,s]  33.5 MB
__device__ float g_Kp[BB*HH*DH*SS];                  // [b,h,kdim,s]  33.5 MB
__device__ __nv_bfloat16 g_Vhi[(size_t)BB*HH*SS*DD]; // [b,h,s,d]     33.5 MB
__device__ __nv_bfloat16 g_Vlo[(size_t)BB*HH*SS*DD]; // [b,h,s,d]     33.5 MB
__device__ float g_inv[DH];

// ---- smem layout (bytes) ----
#define OFF_QST 0            // fp32 Q [64 kdim][128 m]          32768
#define OFF_KS  32768        // fp32 K 2 x [64 kdim][64 n]       32768
#define OFF_VHI 65536        // bf16 Vhi 2 x [64 k][128 d]       34816 (row 272B)
#define OFF_VLO 100352       // bf16 Vlo 2 x                     34816
#define OFF_PHI 135168       // bf16 P  2 x (hi 18432 + lo 18432) = 73728
#define OFF_F   208896       // float f 2 x 128
#define OFF_L   209920       // float l[128]
#define SMEM_TOTAL 210432
#define VROWB 272            // ≡ 4 words mod 32 banks -> conflict-free ldmatrix
#define VTILE 17408          // 64 * 272 (per split per buffer)
#define VLO_DELTA 34816      // OFF_VLO - OFF_VHI
#define PROWB 144            // ≡ 4 words mod 32
#define PBUF 36864           // per P buffer (hi+lo)
#define PLO_DELTA 18432

// ---------------- packed f32x2 helpers (GEMM1) ----------------
__device__ __forceinline__ u64 bcast2(float x) {
    u64 r; asm("mov.b64 %0, {%1, %1};" : "=l"(r) : "f"(x)); return r;
}
__device__ __forceinline__ void ffma2(u64& d, u64 a, u64 b) {
    asm("fma.rn.f32x2 %0, %1, %2, %3;" : "=l"(d) : "l"(a), "l"(b), "l"(d));
}
__device__ __forceinline__ void unpack2(u64 v, float& lo, float& hi) {
    asm("mov.b64 {%0, %1}, %2;" : "=f"(lo), "=f"(hi) : "l"(v));
}

// ---------------- cp.async ----------------
__device__ __forceinline__ void cp_async16(uint32_t saddr, const void* gptr) {
    asm volatile("cp.async.cg.shared.global [%0], [%1], 16;" :: "r"(saddr), "l"(gptr));
}
__device__ __forceinline__ void cp_commit() { asm volatile("cp.async.commit_group;"); }
__device__ __forceinline__ void cp_wait_all() { asm volatile("cp.async.wait_group 0;"); }
__device__ __forceinline__ void cp_wait_1()  { asm volatile("cp.async.wait_group 1;"); }

// ---------------- tensor core: ldmatrix + mma.sync (base PTX) ----------------
__device__ __forceinline__ void ldmx4(uint32_t* r, uint32_t a) {
    asm volatile("ldmatrix.sync.aligned.m8n8.x4.shared.b16 {%0,%1,%2,%3}, [%4];"
        : "=r"(r[0]), "=r"(r[1]), "=r"(r[2]), "=r"(r[3]) : "r"(a));
}
__device__ __forceinline__ void ldmx4t(uint32_t* r, uint32_t a) {
    asm volatile("ldmatrix.sync.aligned.m8n8.x4.trans.shared.b16 {%0,%1,%2,%3}, [%4];"
        : "=r"(r[0]), "=r"(r[1]), "=r"(r[2]), "=r"(r[3]) : "r"(a));
}
__device__ __forceinline__ void mma16816(float* c, const uint32_t* a, const uint32_t* b) {
    asm volatile("mma.sync.aligned.m16n8k16.row.col.f32.bf16.bf16.f32 "
        "{%0,%1,%2,%3}, {%4,%5,%6,%7}, {%8,%9}, {%0,%1,%2,%3};"
        : "+f"(c[0]), "+f"(c[1]), "+f"(c[2]), "+f"(c[3])
        : "r"(a[0]), "r"(a[1]), "r"(a[2]), "r"(a[3]), "r"(b[0]), "r"(b[1]));
}

// ---------------- prep ----------------
__global__ void init_inv() {
    int i = threadIdx.x;
    g_inv[i] = (float)exp(-(double)i * (9.210340371976184 / 64.0)); // ln(1e4)/64
}

__global__ void prep_qk(const float* __restrict__ q, const float* __restrict__ k) {
    __shared__ float qs[64*65];
    __shared__ float ks[64*65];
    const int st = blockIdx.x, h = blockIdx.y, b = blockIdx.z;
    const int tid = threadIdx.x;
    for (int idx = tid; idx < 64*64; idx += 256) {
        int sl = idx >> 6, i = idx & 63;
        int s = st*64 + sl;
        float fc = 2.0f * ((float)s * g_inv[i]);
        size_t gin = ((size_t)(b*SS + s)*HH + h)*DD + i;
        qs[i*65 + sl] = q[gin] * fc;
        ks[i*65 + sl] = k[gin] * fc;
    }
    __syncthreads();
    float* Qo = g_Qp + (size_t)((b*HH + h)*DH)*SS + st*64;
    float* Ko = g_Kp + (size_t)((b*HH + h)*DH)*SS + st*64;
    for (int idx = tid; idx < 64*64; idx += 256) {
        int i = idx >> 6, sl = idx & 63;
        Qo[(size_t)i*SS + sl] = qs[i*65 + sl];
        Ko[(size_t)i*SS + sl] = ks[i*65 + sl];
    }
}

__global__ void prep_v(const float* __restrict__ v) {
    const int st = blockIdx.x, h = blockIdx.y, b = blockIdx.z;
    const int tid = threadIdx.x;
    for (int idx = tid; idx < 64*32; idx += 256) {
        int s = idx >> 5, d4 = idx & 31;
        float4 x = *(const float4*)&v[((size_t)(b*SS + st*64 + s)*HH + h)*DD + d4*4];
        __nv_bfloat16 h0 = __float2bfloat16(x.x), h1 = __float2bfloat16(x.y);
        __nv_bfloat16 h2 = __float2bfloat16(x.z), h3 = __float2bfloat16(x.w);
        __nv_bfloat16 l0 = __float2bfloat16(x.x - __bfloat162float(h0));
        __nv_bfloat16 l1 = __float2bfloat16(x.y - __bfloat162float(h1));
        __nv_bfloat16 l2 = __float2bfloat16(x.z - __bfloat162float(h2));
        __nv_bfloat16 l3 = __float2bfloat16(x.w - __bfloat162float(h3));
        size_t o = ((size_t)(b*HH + h)*SS + st*64 + s)*DD + d4*4;
        __nv_bfloat162* ph = (__nv_bfloat162*)(g_Vhi + o);
        __nv_bfloat162* pl = (__nv_bfloat162*)(g_Vlo + o);
        __nv_bfloat162 a; a.x = h0; a.y = h1; ph[0] = a;
        a.x = h2; a.y = h3; ph[1] = a;
        a.x = l0; a.y = l1; pl[0] = a;
        a.x = l2; a.y = l3; pl[1] = a;
    }
}

// ---------------- attn building blocks ----------------
__device__ __forceinline__ void gemm1_chunk(const float* QsT, const float* KsT,
                                            int ti, int tj, int ks, u64 acc2[4][4]) {
    #pragma unroll
    for (int i = 0; i < 16; i++) {
        int kk = ks*16 + i;
        ulonglong2 a01 = *(const ulonglong2*)&QsT[(kk << 7) + (ti << 3)];
        ulonglong2 a23 = *(const ulonglong2*)&QsT[(kk << 7) + (ti << 3) + 4];
        float4 b4 = *(const float4*)&KsT[(kk << 6) + (tj << 2)];
        u64 b0 = bcast2(b4.x), b1 = bcast2(b4.y);
        u64 b2 = bcast2(b4.z), b3 = bcast2(b4.w);
        ffma2(acc2[0][0], a01.x, b0); ffma2(acc2[0][1], a01.x, b1);
        ffma2(acc2[0][2], a01.x, b2); ffma2(acc2[0][3], a01.x, b3);
        ffma2(acc2[1][0], a01.y, b0); ffma2(acc2[1][1], a01.y, b1);
        ffma2(acc2[1][2], a01.y, b2); ffma2(acc2[1][3], a01.y, b3);
        ffma2(acc2[2][0], a23.x, b0); ffma2(acc2[2][1], a23.x, b1);
        ffma2(acc2[2][2], a23.x, b2); ffma2(acc2[2][3], a23.x, b3);
        ffma2(acc2[3][0], a23.y, b0); ffma2(acc2[3][1], a23.y, b1);
        ffma2(acc2[3][2], a23.y, b2); ffma2(acc2[3][3], a23.y, b3);
    }
}

// GEMM2 chunk for one ks (k16): warp covers 32 rows (2 m-tiles) x 64 d (its half)
__device__ __forceinline__ void gemm2_chunk(uint32_t pa, uint32_t vb, int ks, float* c) {
    uint32_t ko = (uint32_t)(ks*16)*VROWB;
    uint32_t ahi0[4], alo0[4], ahi1[4], alo1[4];
    ldmx4(ahi0, pa + ks*32);
    ldmx4(alo0, pa + PLO_DELTA + ks*32);
    ldmx4(ahi1, pa + 16*PROWB + ks*32);
    ldmx4(alo1, pa + PLO_DELTA + 16*PROWB + ks*32);
    #pragma unroll
    for (int nb = 0; nb < 4; nb++) {
        uint32_t bh[4], bl[4];
        ldmx4t(bh, vb + ko + nb*32);
        ldmx4t(bl, vb + VLO_DELTA + ko + nb*32);
        mma16816(&c[(2*nb)*4],          ahi0, bh);
        mma16816(&c[(2*nb)*4],          ahi0, bl);
        mma16816(&c[(2*nb)*4],          alo0, bh);
        mma16816(&c[(2*nb + 1)*4],      ahi0, bh + 2);
        mma16816(&c[(2*nb + 1)*4],      ahi0, bl + 2);
        mma16816(&c[(2*nb + 1)*4],      alo0, bh + 2);
        mma16816(&c[(8 + 2*nb)*4],      ahi1, bh);
        mma16816(&c[(8 + 2*nb)*4],      ahi1, bl);
        mma16816(&c[(8 + 2*nb)*4],      alo1, bh);
        mma16816(&c[(8 + 2*nb + 1)*4],  ahi1, bh + 2);
        mma16816(&c[(8 + 2*nb + 1)*4],  ahi1, bl + 2);
        mma16816(&c[(8 + 2*nb + 1)*4],  alo1, bh + 2);
    }
}

__device__ __forceinline__ void rescale_c(float* c, const float* fprev, int rg, int lane) {
    #pragma unroll
    for (int mt = 0; mt < 2; mt++) {
        float f0 = fprev[rg*32 + mt*16 + (lane >> 2)];
        float f1 = fprev[rg*32 + mt*16 + (lane >> 2) + 8];
        #pragma unroll
        for (int nt = 0; nt < 8; nt++) {
            c[(mt*8 + nt)*4 + 0] *= f0; c[(mt*8 + nt)*4 + 1] *= f0;
            c[(mt*8 + nt)*4 + 2] *= f1; c[(mt*8 + nt)*4 + 3] *= f1;
        }
    }
}

__device__ __forceinline__ void softmax_tile(u64 acc2[4][4], float* mrow, float* lrow,
                                             char* smem, uint32_t phi_off, float* fptr,
                                             int ti, int tj) {
    float p[8][4];
    #pragma unroll
    for (int mp = 0; mp < 4; mp++)
        #pragma unroll
        for (int n = 0; n < 4; n++)
            unpack2(acc2[mp][n], p[2*mp][n], p[2*mp + 1][n]);

    const float sc2 = 1.44269504088896340736f / 64.0f;  // log2(e)/64

    float mx[8];
    #pragma unroll
    for (int r = 0; r < 8; r++)
        mx[r] = fmaxf(fmaxf(p[r][0], p[r][1]), fmaxf(p[r][2], p[r][3]));
    #pragma unroll
    for (int st = 1; st < 16; st <<= 1)
        #pragma unroll
        for (int r = 0; r < 8; r++)
            mx[r] = fmaxf(mx[r], __shfl_xor_sync(0xffffffffu, mx[r], st));

    float fr[8];
    #pragma unroll
    for (int r = 0; r < 8; r++) {
        float mn = fmaxf(mrow[r], mx[r]*sc2);
        fr[r] = exp2f(mrow[r] - mn);   // 0 on first tile
        mrow[r] = mn;
    }

    float sr[8];
    #pragma unroll
    for (int r = 0; r < 8; r++) {
        #pragma unroll
        for (int cx = 0; cx < 4; cx++)
            p[r][cx] = exp2f(fmaf(p[r][cx], sc2, -mrow[r]));
        sr[r] = (p[r][0] + p[r][1]) + (p[r][2] + p[r][3]);

        int rr = ti*8 + r;
        __nv_bfloat16 h0 = __float2bfloat16(p[r][0]), h1 = __float2bfloat16(p[r][1]);
        __nv_bfloat16 h2 = __float2bfloat16(p[r][2]), h3 = __float2bfloat16(p[r][3]);
        __nv_bfloat162 hh01; hh01.x = h0; hh01.y = h1;
        __nv_bfloat162 hh23; hh23.x = h2; hh23.y = h3;
        __nv_bfloat162 ll01, ll23;
        ll01.x = __float2bfloat16(p[r][0] - __bfloat162float(h0));
        ll01.y = __float2bfloat16(p[r][1] - __bfloat162float(h1));
        ll23.x = __float2bfloat16(p[r][2] - __bfloat162float(h2));
        ll23.y = __float2bfloat16(p[r][3] - __bfloat162float(h3));
        *(uint2*)(smem + phi_off + rr*PROWB + tj*8) =
            make_uint2(*(uint32_t*)&hh01, *(uint32_t*)&hh23);
        *(uint2*)(smem + phi_off + PLO_DELTA + rr*PROWB + tj*8) =
            make_uint2(*(uint32_t*)&ll01, *(uint32_t*)&ll23);
        if (tj == 0) fptr[rr] = fr[r];
    }
    #pragma unroll
    for (int st = 1; st < 16; st <<= 1)
        #pragma unroll
        for (int r = 0; r < 8; r++)
            sr[r] += __shfl_xor_sync(0xffffffffu, sr[r], st);
    #pragma unroll
    for (int r = 0; r < 8; r++)
        lrow[r] = lrow[r]*fr[r] + sr[r];
}

// ---------------- flash attention: pipelined FFMA2 GEMM1 + HMMA GEMM2 ----------------
// 8 warps. GEMM1/softmax: thread (ti,tj). GEMM2: warp = (rg = wid&3 -> 32 rows,
// dh = wid>>2 -> 64-d half). GEMM2 runs one tile behind, fused with GEMM1.
__global__ __launch_bounds__(256, 1)
void attn_kernel(float* __restrict__ out) {
    extern __shared__ char smem[];
    const uint32_t sbase = (uint32_t)__cvta_generic_to_shared(smem);
    float* QsT = (float*)(smem + OFF_QST);
    float* lptr = (float*)(smem + OFF_L);

    const int qt = blockIdx.x, h = blockIdx.y, b = blockIdx.z;
    const int tid = threadIdx.x;
    const int wid = tid >> 5, lane = tid & 31;
    const int ti = tid >> 4, tj = tid & 15;
    const int rg = wid & 3, dh = wid >> 2;

    const float* Qg  = g_Qp + (size_t)((b*HH + h)*DH)*SS + qt*BM;
    const float* Kg0 = g_Kp + (size_t)((b*HH + h)*DH)*SS;
    const __nv_bfloat16* Vh0 = g_Vhi + (size_t)(b*HH + h)*SS*DD;
    const __nv_bfloat16* Vl0 = g_Vlo + (size_t)(b*HH + h)*SS*DD;

    // warp-fixed GEMM2 base addresses (buffer offsets added per tile)
    const uint32_t pa_base = sbase + OFF_PHI + (uint32_t)(rg*32 + (lane & 15))*PROWB
                           + ((lane >> 4) << 4);
    const uint32_t vb_base = sbase + OFF_VHI + (uint32_t)(lane & 15)*VROWB
                           + ((lane >> 4) << 4) + (uint32_t)dh*128;

    // ---- prologue: Q + K0 + V0 ----
    #pragma unroll
    for (int it = 0; it < 8; it++) {
        int idx4 = tid + it*256;
        int kk = idx4 >> 5, m4 = idx4 & 31;
        cp_async16(sbase + OFF_QST + (uint32_t)idx4*16, Qg + (size_t)kk*SS + m4*4);
    }
    #pragma unroll
    for (int it = 0; it < 4; it++) {
        int idx4 = tid + it*256;
        int kk = idx4 >> 4, n4 = idx4 & 15;
        cp_async16(sbase + OFF_KS + (uint32_t)idx4*16, Kg0 + (size_t)kk*SS + n4*4);
    }
    #pragma unroll
    for (int it = 0; it < 4; it++) {
        int idx = tid + it*256;
        int row = idx >> 4, cc = idx & 15;
        cp_async16(sbase + OFF_VHI + (uint32_t)row*VROWB + cc*16, Vh0 + (size_t)row*DD + cc*8);
        cp_async16(sbase + OFF_VLO + (uint32_t)row*VROWB + cc*16, Vl0 + (size_t)row*DD + cc*8);
    }
    cp_commit();

    float mrow[8], lrow[8];
    #pragma unroll
    for (int r = 0; r < 8; r++) { mrow[r] = -INFINITY; lrow[r] = 0.0f; }

    float c[64];
    #pragma unroll
    for (int i = 0; i < 64; i++) c[i] = 0.0f;

    // ---- peel kt = 0 ----
    cp_wait_all();
    __syncthreads();
    {   // prefetch K1
        const float* Kg = Kg0 + BN;
        uint32_t kd = sbase + OFF_KS + 16384;
        #pragma unroll
        for (int it = 0; it < 4; it++) {
            int idx4 = tid + it*256;
            int kk = idx4 >> 4, n4 = idx4 & 15;
            cp_async16(kd + (uint32_t)idx4*16, Kg + (size_t)kk*SS + n4*4);
        }
        cp_commit();
    }
    {
        u64 acc2[4][4];
        #pragma unroll
        for (int mp = 0; mp < 4; mp++)
            #pragma unroll
            for (int n = 0; n < 4; n++) acc2[mp][n] = 0ULL;
        #pragma unroll
        for (int ks = 0; ks < 4; ks++)
            gemm1_chunk(QsT, (const float*)(smem + OFF_KS), ti, tj, ks, acc2);
        // prefetch V1 (buf1 is free; no barrier needed on first tile)
        {
            const __nv_bfloat16* Vh = Vh0 + (size_t)BN*DD;
            const __nv_bfloat16* Vl = Vl0 + (size_t)BN*DD;
            #pragma unroll
            for (int it = 0; it < 4; it++) {
                int idx = tid + it*256;
                int row = idx >> 4, cc = idx & 15;
                cp_async16(sbase + OFF_VHI + VTILE + (uint32_t)row*VROWB + cc*16,
                           Vh + (size_t)row*DD + cc*8);
                cp_async16(sbase + OFF_VLO + VTILE + (uint32_t)row*VROWB + cc*16,
                           Vl + (size_t)row*DD + cc*8);
            }
            cp_commit();
        }
        softmax_tile(acc2, mrow, lrow, smem, OFF_PHI, (float*)(smem + OFF_F), ti, tj);
    }

    // ---- main loop: kt = 1..31; GEMM2 runs on tile kt-1 ----
    for (int kt = 1; kt < SS/BN; ++kt) {
        cp_wait_1();         // K[kt] (and V[kt-?]) done; newest group V[kt] may fly
        __syncthreads();     // orders P[kt-1]/f[kt-1] stores and prev compute

        if (kt + 1 < SS/BN) {  // prefetch K[kt+1]
            const float* Kg = Kg0 + (kt + 1)*BN;
            uint32_t kd = sbase + OFF_KS + (uint32_t)((kt + 1) & 1)*16384;
            #pragma unroll
            for (int it = 0; it < 4; it++) {
                int idx4 = tid + it*256;
                int kk = idx4 >> 4, n4 = idx4 & 15;
                cp_async16(kd + (uint32_t)idx4*16, Kg + (size_t)kk*SS + n4*4);
            }
        }
        cp_commit();

        const float* KsT = (const float*)(smem + OFF_KS + (uint32_t)(kt & 1)*16384);
        const float* fprev = (const float*)(smem + OFF_F + (uint32_t)((kt - 1) & 1)*512);
        const uint32_t pa = pa_base + (uint32_t)((kt - 1) & 1)*PBUF;
        const uint32_t vb = vb_base + (uint32_t)((kt - 1) & 1)*VTILE;

        rescale_c(c, fprev, rg, lane);

        u64 acc2[4][4];
        #pragma unroll
        for (int mp = 0; mp < 4; mp++)
            #pragma unroll
            for (int n = 0; n < 4; n++) acc2[mp][n] = 0ULL;

        #pragma unroll
        for (int ks = 0; ks < 4; ks++) {
            gemm1_chunk(QsT, KsT, ti, tj, ks, acc2);   // fma pipe
            gemm2_chunk(pa, vb, ks, c);                // tensor pipe (tile kt-1)
        }

        __syncthreads();   // all warps done reading V[kt-1] before overwriting its buffer

        if (kt + 1 < SS/BN) {  // prefetch V[kt+1] into buffer (kt+1)&1 == (kt-1)&1
            const __nv_bfloat16* Vh = Vh0 + (size_t)((kt + 1)*BN)*DD;
            const __nv_bfloat16* Vl = Vl0 + (size_t)((kt + 1)*BN)*DD;
            uint32_t vh = sbase + OFF_VHI + (uint32_t)((kt + 1) & 1)*VTILE;
            uint32_t vl = sbase + OFF_VLO + (uint32_t)((kt + 1) & 1)*VTILE;
            #pragma unroll
            for (int it = 0; it < 4; it++) {
                int idx = tid + it*256;
                int row = idx >> 4, cc = idx & 15;
                cp_async16(vh + (uint32_t)row*VROWB + cc*16, Vh + (size_t)row*DD + cc*8);
                cp_async16(vl + (uint32_t)row*VROWB + cc*16, Vl + (size_t)row*DD + cc*8);
            }
        }
        cp_commit();

        softmax_tile(acc2, mrow, lrow, smem,
                     OFF_PHI + (uint32_t)(kt & 1)*PBUF,
                     (float*)(smem + OFF_F + (uint32_t)(kt & 1)*512), ti, tj);
    }

    // ---- tail: GEMM2 for last tile (kt = 31) ----
    cp_wait_all();
    __syncthreads();   // P[31]/f[31] visible
    {
        const int lt = (SS/BN - 1) & 1;
        rescale_c(c, (const float*)(smem + OFF_F + (uint32_t)lt*512), rg, lane);
        const uint32_t pa = pa_base + (uint32_t)lt*PBUF;
        const uint32_t vb = vb_base + (uint32_t)lt*VTILE;
        #pragma unroll
        for (int ks = 0; ks < 4; ks++)
            gemm2_chunk(pa, vb, ks, c);
    }

    // ---- epilogue: publish l, normalize, store ----
    if (tj == 0) {
        #pragma unroll
        for (int r = 0; r < 8; r++) lptr[ti*8 + r] = lrow[r];
    }
    __syncthreads();
    #pragma unroll
    for (int mt = 0; mt < 2; mt++) {
        int rloc = rg*32 + mt*16 + (lane >> 2);
        float il0 = 1.0f / lptr[rloc];
        float il1 = 1.0f / lptr[rloc + 8];
        int r0 = qt*BM + rloc;
        float* op0 = out + (((size_t)b*SS + r0)*HH + h)*DD + dh*64 + (lane & 3)*2;
        float* op1 = op0 + (size_t)8*HH*DD;   // row+8 -> s+8
        #pragma unroll
        for (int nt = 0; nt < 8; nt++) {
            int ci = (mt*8 + nt)*4;
            *(float2*)(op0 + nt*8) = make_float2(c[ci + 0]*il0, c[ci + 1]*il0);
            *(float2*)(op1 + nt*8) = make_float2(c[ci + 2]*il1, c[ci + 3]*il1);
        }
    }
}

extern "C" void kernel_launch(void* const* d_in, const int* in_sizes, int n_in,
                              void* d_out, int out_size) {
    const float* q = (const float*)d_in[0];
    const float* k = (const float*)d_in[1];
    const float* v = (const float*)d_in[2];
    float* out = (float*)d_out;

    cudaFuncSetAttribute(attn_kernel, cudaFuncAttributeMaxDynamicSharedMemorySize, SMEM_TOTAL);

    init_inv<<<1, 64>>>();
    dim3 pgrid(SS/64, HH, BB);
    prep_qk<<<pgrid, 256>>>(q, k);
    prep_v<<<pgrid, 256>>>(v);

    dim3 grid(SS/BM, HH, BB);
    attn_kernel<<<grid, 256, SMEM_TOTAL>>>(out);
}